// round 17
// baseline (speedup 1.0000x reference)
#include <cuda_runtime.h>
#include <math.h>

#define SLEN   2048
#define HEADS  32
#define DHEAD  128
#define TQ     64
#define TK     64
#define NT     128
#define QPITCH 33   // odd float4 pitch: distinct banks for the per-warp row pair

// ---------------- shared memory layout (101.5 KB -> 2 CTAs/SM) ----------------
// Qs: [64 rows][pitch 33 float4] LINEAR (loads are ty-broadcast, stores lane-
//     linear). Zero address ALU on Q loads.
// KA/KB: [64 rows][32 float4], XOR swizzle phys_d4 = d4 ^ (row & 7).
//        Pass 1: K ping-pong. Pass 2: KA = K tile, KB = V tile.
// Wu: packed u8 weights [64 k-cols][pitch 18 words]; words c*18+2ty, +1 hold
//     rows 8ty..8ty+7.
struct __align__(16) Smem {
    float4   Qs[TQ * QPITCH];   // 33792 B
    float4   KA[TK * 32];       // 32768 B
    float4   KB[TK * 32];       // 32768 B
    unsigned Wu[TK * 18];       //  4608 B
};

// f32 exp(x) for |x| <= 0.4 (~0.5 ulp), pass 1 only (feeds fp64 sum).
__device__ __forceinline__ float expP(float x)
{
    float p = 1.0f / 5040.0f;
    p = fmaf(p, x, 1.0f / 720.0f);
    p = fmaf(p, x, 1.0f / 120.0f);
    p = fmaf(p, x, 1.0f / 24.0f);
    p = fmaf(p, x, 1.0f / 6.0f);
    p = fmaf(p, x, 0.5f);
    p = fmaf(p, x, 1.0f);
    return fmaf(p, x, 1.0f);
}

// Correctly-rounded f32 exp for t in [-0.4, 0]: degree-10 Taylor in double,
// single rounding to f32 (bit-matches correctly-rounded libm expf). Pass 2.
__device__ __forceinline__ float expCR(float t)
{
    const double x = (double)t;
    double p = 1.0 / 3628800.0;
    p = fma(p, x, 1.0 / 362880.0);
    p = fma(p, x, 1.0 / 40320.0);
    p = fma(p, x, 1.0 / 5040.0);
    p = fma(p, x, 1.0 / 720.0);
    p = fma(p, x, 1.0 / 120.0);
    p = fma(p, x, 1.0 / 24.0);
    p = fma(p, x, 1.0 / 6.0);
    p = fma(p, x, 0.5);
    p = fma(p, x, 1.0);
    p = fma(p, x, 1.0);
    return (float)p;
}

// 64x64x128 fp32 GEMM, 8x4 micro-tile: s[i][u] = dot(Q row 8*ty+i, K row tx+16*u)
// Each s[i][u] is a single-accumulator fmaf chain over ascending d (x,y,z,w
// within float4) == Eigen gebp order; identical chains in both passes.
__device__ __forceinline__ void gemm_qk(const float4* __restrict__ Qs,
                                        const float4* __restrict__ Ks,
                                        int tx, int ty, float s[8][4])
{
    #pragma unroll
    for (int i = 0; i < 8; ++i)
        #pragma unroll
        for (int u = 0; u < 4; ++u)
            s[i][u] = 0.0f;

    const float4* qp  = Qs + (8 * ty) * QPITCH;
    const int     xk  = tx & 7;
    const float4* kp0 = Ks + (tx     ) * 32;
    const float4* kp1 = Ks + (tx + 16) * 32;
    const float4* kp2 = Ks + (tx + 32) * 32;
    const float4* kp3 = Ks + (tx + 48) * 32;

    #pragma unroll 4
    for (int d4 = 0; d4 < 32; ++d4) {
        float4 q4[8], k4[4];
        #pragma unroll
        for (int i = 0; i < 8; ++i)
            q4[i] = qp[i * QPITCH + d4];  // immediate-offset LDS, 2-addr broadcast
        const int kd = d4 ^ xk;           // one LOP3 shared by 4 K loads
        k4[0] = kp0[kd];
        k4[1] = kp1[kd];
        k4[2] = kp2[kd];
        k4[3] = kp3[kd];
        #pragma unroll
        for (int i = 0; i < 8; ++i)
            #pragma unroll
            for (int u = 0; u < 4; ++u) {
                s[i][u] = fmaf(q4[i].x, k4[u].x, s[i][u]);
                s[i][u] = fmaf(q4[i].y, k4[u].y, s[i][u]);
                s[i][u] = fmaf(q4[i].z, k4[u].z, s[i][u]);
                s[i][u] = fmaf(q4[i].w, k4[u].w, s[i][u]);
            }
    }
}

// Non-diagonal tiles: v = s*norm + am only (exact ref op order, no mask).
__device__ __forceinline__ void scale_add(float s[8][4], float v[8][4],
                                          const float* __restrict__ am,
                                          int kb, int tx, float norm)
{
    float amv[4];
    #pragma unroll
    for (int u = 0; u < 4; ++u) amv[u] = __ldg(&am[kb + tx + 16 * u]);

    #pragma unroll
    for (int i = 0; i < 8; ++i)
        #pragma unroll
        for (int u = 0; u < 4; ++u)
            v[i][u] = __fadd_rn(__fmul_rn(s[i][u], norm), amv[u]);
}

// Diagonal tile: same arithmetic + causal mask flags.
__device__ __forceinline__ void scale_mask(float s[8][4], float v[8][4], int dead[8][4],
                                           const float* __restrict__ am,
                                           int kb, int tx, int ty, int q0, float norm)
{
    float amv[4];
    #pragma unroll
    for (int u = 0; u < 4; ++u) amv[u] = __ldg(&am[kb + tx + 16 * u]);

    #pragma unroll
    for (int i = 0; i < 8; ++i) {
        const int qr = q0 + 8 * ty + i;
        #pragma unroll
        for (int u = 0; u < 4; ++u) {
            const int kc = kb + tx + 16 * u;
            v[i][u] = __fadd_rn(__fmul_rn(s[i][u], norm), amv[u]);
            dead[i][u] = kc > qr;
        }
    }
}

__global__ void __launch_bounds__(NT, 2)
attn_kernel(const float* __restrict__ Q, const float* __restrict__ K,
            const float* __restrict__ V, const float* __restrict__ AM,
            float* __restrict__ O)
{
    extern __shared__ float4 smem_raw[];
    Smem& sm = *reinterpret_cast<Smem*>(smem_raw);

    const int tid = threadIdx.x;
    const int tx  = tid & 15;        // 16 column-group lanes
    const int ty  = tid >> 4;        // 8 row groups of 8
    const int qt  = (int)gridDim.x - 1 - (int)blockIdx.x;  // heavy tiles first
    const int bh  = (int)blockIdx.y;
    const int b   = bh >> 5;
    const int h   = bh & 31;
    const int q0  = qt * TQ;

    // norm exactly as numpy computes it, rounding at every f32 step.
    const float sq128 = (float)11.313708498984761;   // f32(np.sqrt(128))
    const float norm  = __fmul_rn(__fmul_rn(__fdiv_rn(1.0f, sq128), 0.1f), 0.1f);
    const float c1    = (float)((1.0 / 255.0) * (1.0 / 10.0));

    const size_t base = (size_t)bh * SLEN * DHEAD;
    const float* am   = AM + (size_t)b * SLEN;
    const float4* gq  = reinterpret_cast<const float4*>(Q + base) + (size_t)q0 * (DHEAD / 4);
    const float4* gk0 = reinterpret_cast<const float4*>(K + base);
    const float4* gv0 = reinterpret_cast<const float4*>(V + base);

    // ---- load Q tile: coalesced, LINEAR pitch-33 store (conflict-free) ----
    #pragma unroll
    for (int j = 0; j < 16; ++j) {
        const int i = tid + NT * j;
        sm.Qs[(i >> 5) * QPITCH + (i & 31)] = gq[i];
    }

    // Per-thread partial stats (reduced across lanes once after pass 1).
    double Lp[8];
    float  mloc[8];
    #pragma unroll
    for (int i = 0; i < 8; ++i) { Lp[i] = 0.0; mloc[i] = -3.402823466e38f; }

    // ========== pass 1: K ping-pong, ONE barrier/tile, diag specialized ==========
    {
        float4* const buf[2] = { sm.KA, sm.KB };

        float4 pk[16];
        #pragma unroll
        for (int j = 0; j < 16; ++j) pk[j] = gk0[tid + NT * j];
        #pragma unroll
        for (int j = 0; j < 16; ++j) {
            const int i = tid + NT * j;
            const int r = i >> 5, d4 = i & 31;
            sm.KA[r * 32 + (d4 ^ (r & 7))] = pk[j];
        }
        __syncthreads();

        int p = 0;
        for (int kt = 0; kt < qt; ++kt) {        // NON-diagonal tiles only
            {   // prefetch next K tile (LDG hidden by GEMM)
                const float4* gk = gk0 + (size_t)(kt + 1) * TK * (DHEAD / 4);
                #pragma unroll
                for (int j = 0; j < 16; ++j) pk[j] = gk[tid + NT * j];
            }

            float s[8][4];
            gemm_qk(sm.Qs, buf[p], tx, ty, s);

            {   // stage next tile in the OTHER buffer (no race)
                float4* dst = buf[p ^ 1];
                #pragma unroll
                for (int j = 0; j < 16; ++j) {
                    const int i = tid + NT * j;
                    const int r = i >> 5, d4 = i & 31;
                    dst[r * 32 + (d4 ^ (r & 7))] = pk[j];
                }
            }

            float v[8][4];
            scale_add(s, v, am, kt * TK, tx, norm);

            #pragma unroll
            for (int i = 0; i < 8; ++i) {
                const float e0 = expP(v[i][0]);
                const float e1 = expP(v[i][1]);
                const float e2 = expP(v[i][2]);
                const float e3 = expP(v[i][3]);
                Lp[i] += (double)((e0 + e1) + (e2 + e3));
                mloc[i] = fmaxf(mloc[i],
                                fmaxf(fmaxf(v[i][0], v[i][1]),
                                      fmaxf(v[i][2], v[i][3])));
            }

            __syncthreads();     // publishes buf[p^1]
            p ^= 1;
        }

        // ---- diagonal tile (kt == qt), masked path ----
        {
            float s[8][4];
            gemm_qk(sm.Qs, buf[p], tx, ty, s);
            float v[8][4]; int dead[8][4];
            scale_mask(s, v, dead, am, qt * TK, tx, ty, q0, norm);

            #pragma unroll
            for (int i = 0; i < 8; ++i) {
                const float e0 = dead[i][0] ? 0.0f : expP(v[i][0]);
                const float e1 = dead[i][1] ? 0.0f : expP(v[i][1]);
                const float e2 = dead[i][2] ? 0.0f : expP(v[i][2]);
                const float e3 = dead[i][3] ? 0.0f : expP(v[i][3]);
                Lp[i] += (double)((e0 + e1) + (e2 + e3));

                const float t0 = dead[i][0] ? -3.402823466e38f : v[i][0];
                const float t1 = dead[i][1] ? -3.402823466e38f : v[i][1];
                const float t2 = dead[i][2] ? -3.402823466e38f : v[i][2];
                const float t3 = dead[i][3] ? -3.402823466e38f : v[i][3];
                mloc[i] = fmaxf(mloc[i], fmaxf(fmaxf(t0, t1), fmaxf(t2, t3)));
            }
        }
    }

    // ---- one-time cross-lane reduction (16 tx lanes in each half-warp) ----
    double L[8];
    float  m[8];
    #pragma unroll
    for (int i = 0; i < 8; ++i) {
        float t = mloc[i];
        #pragma unroll
        for (int msk = 1; msk < 16; msk <<= 1)
            t = fmaxf(t, __shfl_xor_sync(0xffffffffu, t, msk));
        m[i] = t;                                   // exact f32 row max

        double rs = Lp[i];
        #pragma unroll
        for (int msk = 1; msk < 16; msk <<= 1)
            rs += __shfl_xor_sync(0xffffffffu, rs, msk);
        L[i] = rs;
    }

    // ---- l in f32 (value the ref divides by): l = L * exp(-m), near-exact ----
    float lf[8];
    int needp = 0;
    #pragma unroll
    for (int i = 0; i < 8; ++i) {
        lf[i] = (float)(L[i] * exp(-(double)m[i]));
        // skip test with EXACTLY the pass-2 weight arithmetic at e = 1
        // (argmax element has e = expCR(0) = 1); weights monotone in e.
        const float zmax = __fmul_rn(__fdiv_rn(1.0f, lf[i]), 255.0f);
        if (rintf(zmax) >= 1.0f) needp = 1;
    }
    const int need = __syncthreads_or(needp);

    if (!need) {
        // whole tile quantizes to zero — write zeros (out is poisoned)
        const float4 z = make_float4(0.f, 0.f, 0.f, 0.f);
        #pragma unroll
        for (int i = 0; i < 8; ++i) {
            const int row = q0 + 8 * ty + i;
            float4* p = reinterpret_cast<float4*>(
                O + ((size_t)b * SLEN + row) * (HEADS * DHEAD) + h * DHEAD + 8 * tx);
            p[0] = z; p[1] = z;
        }
        return;
    }

    // ================= pass 2: quantized weights + W @ V =================
    // fp32 accumulators, fmaf in STRICTLY ascending global k order
    // (Eigen-sequential emulation; zero weights add exactly 0).
    float acc[8][8];
    #pragma unroll
    for (int i = 0; i < 8; ++i)
        #pragma unroll
        for (int jj = 0; jj < 8; ++jj) acc[i][jj] = 0.0f;

    for (int kt = 0; kt <= qt; ++kt) {
        __syncthreads();   // previous iteration's KB/Wu readers done
        {
            const float4* gk = gk0 + (size_t)kt * TK * (DHEAD / 4);
            const float4* gv = gv0 + (size_t)kt * TK * (DHEAD / 4);
            #pragma unroll
            for (int j = 0; j < 16; ++j) {
                const int i = tid + NT * j;
                const int r = i >> 5, d4 = i & 31;
                const int idx = r * 32 + (d4 ^ (r & 7));
                sm.KA[idx] = gk[i];
                sm.KB[idx] = gv[i];    // V tile
            }
        }
        __syncthreads();

        float s[8][4];
        gemm_qk(sm.Qs, sm.KA, tx, ty, s);                  // identical to pass 1
        float v[8][4];
        const bool diag = (kt == qt);

        if (!diag) {
            scale_add(s, v, am, kt * TK, tx, norm);
            // w = clip(rint(f32(f32(expCR(f32(v-m)) / l) * 255)), 0, 255)
            #pragma unroll
            for (int u = 0; u < 4; ++u) {
                const int c = tx + 16 * u;
                unsigned pw0 = 0, pw1 = 0;
                #pragma unroll
                for (int i = 0; i < 4; ++i) {
                    const float t2 = __fadd_rn(v[i][u], -m[i]);  // f32 (s - max)
                    const float e  = expCR(t2);                  // = 1.0f at argmax
                    const float z  = __fmul_rn(__fdiv_rn(e, lf[i]), 255.0f);
                    pw0 |= ((unsigned)fminf(rintf(z), 255.0f)) << (8 * i);
                }
                #pragma unroll
                for (int i = 4; i < 8; ++i) {
                    const float t2 = __fadd_rn(v[i][u], -m[i]);
                    const float e  = expCR(t2);
                    const float z  = __fmul_rn(__fdiv_rn(e, lf[i]), 255.0f);
                    pw1 |= ((unsigned)fminf(rintf(z), 255.0f)) << (8 * (i - 4));
                }
                sm.Wu[c * 18 + 2 * ty]     = pw0;
                sm.Wu[c * 18 + 2 * ty + 1] = pw1;
            }
        } else {
            int dead[8][4];
            scale_mask(s, v, dead, am, kt * TK, tx, ty, q0, norm);
            #pragma unroll
            for (int u = 0; u < 4; ++u) {
                const int c = tx + 16 * u;
                unsigned pw0 = 0, pw1 = 0;
                #pragma unroll
                for (int i = 0; i < 8; ++i) {
                    float w;
                    if (dead[i][u]) {
                        w = 0.0f;
                    } else {
                        const float t2 = __fadd_rn(v[i][u], -m[i]);
                        const float e  = expCR(t2);
                        const float z  = __fmul_rn(__fdiv_rn(e, lf[i]), 255.0f);
                        w = fminf(rintf(z), 255.0f);
                    }
                    if (i < 4) pw0 |= ((unsigned)w) << (8 * i);
                    else       pw1 |= ((unsigned)w) << (8 * (i - 4));
                }
                sm.Wu[c * 18 + 2 * ty]     = pw0;
                sm.Wu[c * 18 + 2 * ty + 1] = pw1;
            }
        }
        __syncthreads();

        // acc[r][d] += W[r][c] * V[c][d], c ascending (global k ascending).
        // Weights are exact small integers: u8 -> f32 conversion is exact.
        #pragma unroll 4
        for (int c = 0; c < 64; ++c) {
            const uint2 pw = *reinterpret_cast<const uint2*>(&sm.Wu[c * 18 + 2 * ty]);
            const float4 v0 = sm.KB[c * 32 + ((2 * tx)     ^ (c & 7))];
            const float4 v1 = sm.KB[c * 32 + ((2 * tx + 1) ^ (c & 7))];
            float wv[8];
            wv[0] = (float)(int)__byte_perm(pw.x, 0, 0x4440);
            wv[1] = (float)(int)__byte_perm(pw.x, 0, 0x4441);
            wv[2] = (float)(int)__byte_perm(pw.x, 0, 0x4442);
            wv[3] = (float)(int)__byte_perm(pw.x, 0, 0x4443);
            wv[4] = (float)(int)__byte_perm(pw.y, 0, 0x4440);
            wv[5] = (float)(int)__byte_perm(pw.y, 0, 0x4441);
            wv[6] = (float)(int)__byte_perm(pw.y, 0, 0x4442);
            wv[7] = (float)(int)__byte_perm(pw.y, 0, 0x4443);
            #pragma unroll
            for (int i = 0; i < 8; ++i) {
                acc[i][0] = fmaf(wv[i], v0.x, acc[i][0]);
                acc[i][1] = fmaf(wv[i], v0.y, acc[i][1]);
                acc[i][2] = fmaf(wv[i], v0.z, acc[i][2]);
                acc[i][3] = fmaf(wv[i], v0.w, acc[i][3]);
                acc[i][4] = fmaf(wv[i], v1.x, acc[i][4]);
                acc[i][5] = fmaf(wv[i], v1.y, acc[i][5]);
                acc[i][6] = fmaf(wv[i], v1.z, acc[i][6]);
                acc[i][7] = fmaf(wv[i], v1.w, acc[i][7]);
            }
        }
    }

    // ---- epilogue: exact ref op order on the emulated f32 einsum result ----
    #pragma unroll
    for (int i = 0; i < 8; ++i) {
        float o[8];
        #pragma unroll
        for (int jj = 0; jj < 8; ++jj) {
            float y = __fmul_rn(acc[i][jj], c1);   // out * f32(1/2550)
            y = __fmul_rn(y, 127.0f);              // * REQUANT
            y = rintf(y);                          // round half-to-even
            o[jj] = fminf(fmaxf(y, -128.0f), 127.0f);
        }
        const int row = q0 + 8 * ty + i;
        float4* p = reinterpret_cast<float4*>(
            O + ((size_t)b * SLEN + row) * (HEADS * DHEAD) + h * DHEAD + 8 * tx);
        p[0] = make_float4(o[0], o[1], o[2], o[3]);
        p[1] = make_float4(o[4], o[5], o[6], o[7]);
    }
}

extern "C" void kernel_launch(void* const* d_in, const int* in_sizes, int n_in,
                              void* d_out, int out_size)
{
    (void)in_sizes; (void)n_in; (void)out_size;
    const float* q  = (const float*)d_in[0];
    const float* k  = (const float*)d_in[1];
    const float* v  = (const float*)d_in[2];
    const float* am = (const float*)d_in[3];
    float* out = (float*)d_out;

    const int smem = (int)sizeof(Smem);   // 103936 B -> 2 CTAs/SM
    cudaFuncSetAttribute(attn_kernel, cudaFuncAttributeMaxDynamicSharedMemorySize, smem);

    dim3 grid(SLEN / TQ, 2 * HEADS);      // (32 q-tiles, 64 batch*head)
    attn_kernel<<<grid, NT, smem>>>(q, k, v, am, out);
}